// round 10
// baseline (speedup 1.0000x reference)
#include <cuda_runtime.h>
#include <cuda_bf16.h>
#include <cstdint>

// Problem shape (fixed)
#define MDIM 512            // reduction dim
#define KDIM 256            // output cols (w rows)
#define MROWS 2048          // output rows (B*N)

#define NSLICE 4
#define SLICE_ROWB 256      // bytes per row per slice (128 bf16)

// GEMM tiling
#define BM 64
#define BN 64
#define A_SL_BYTES (BM * SLICE_ROWB)     // 16384
#define B_SL_BYTES (BN * SLICE_ROWB)     // 16384
#define SM_A_OFF 1024
#define SM_B_OFF (SM_A_OFF + NSLICE * A_SL_BYTES)    // 66560
#define SMEM_TOTAL (SM_B_OFF + NSLICE * B_SL_BYTES)  // 132096
#define SM_ROWSUM 32        // 64 floats at sbase+32

// Scratch: only w. bf16, slice-major, per-row 16B-chunk swizzle:
//   addr(row r, slice s, chunk c, half h) = (s*KDIM + r)*256 + ((c^(r&7))<<4) + h*8
__device__ __align__(16) __nv_bfloat16 g_wq[KDIM * MDIM];    // 256 KB
__device__ float g_colsum[KDIM];

// ---------------------------------------------------------------------------
__device__ __forceinline__ float quantize1(float v, float s, float zp) {
    float q = rintf(__fadd_rn(__fdiv_rn(v, s), zp));
    return fminf(fmaxf(q, -128.0f), 127.0f);
}
__device__ __forceinline__ uint32_t smem_u32(const void* p) {
    return (uint32_t)__cvta_generic_to_shared(p);
}
__device__ __forceinline__ void ldsm_x4(uint32_t& r0, uint32_t& r1,
                                        uint32_t& r2, uint32_t& r3, uint32_t addr) {
    asm volatile("ldmatrix.sync.aligned.m8n8.x4.shared.b16 {%0,%1,%2,%3}, [%4];"
                 : "=r"(r0), "=r"(r1), "=r"(r2), "=r"(r3) : "r"(addr));
}
__device__ __forceinline__ void mma16816(float& c0, float& c1, float& c2, float& c3,
                                         uint32_t a0, uint32_t a1, uint32_t a2, uint32_t a3,
                                         uint32_t b0, uint32_t b1) {
    asm volatile(
        "mma.sync.aligned.m16n8k16.row.col.f32.bf16.bf16.f32 "
        "{%0,%1,%2,%3}, {%4,%5,%6,%7}, {%8,%9}, {%0,%1,%2,%3};"
        : "+f"(c0), "+f"(c1), "+f"(c2), "+f"(c3)
        : "r"(a0), "r"(a1), "r"(a2), "r"(a3), "r"(b0), "r"(b1));
}
__device__ __forceinline__ void bulk_copy(uint32_t sdst, const void* gsrc,
                                          uint32_t bytes, uint32_t mbar) {
    asm volatile(
        "cp.async.bulk.shared::cluster.global.mbarrier::complete_tx::bytes "
        "[%0], [%1], %2, [%3];"
        :: "r"(sdst), "l"(gsrc), "r"(bytes), "r"(mbar) : "memory");
}
__device__ __forceinline__ void mbar_wait0(uint32_t mbar) {
    asm volatile(
        "{\n\t"
        ".reg .pred P1;\n\t"
        "WAIT_LOOP_%=:\n\t"
        "mbarrier.try_wait.parity.acquire.cta.shared::cta.b64 P1, [%0], 0, 0x989680;\n\t"
        "@P1 bra.uni WAIT_DONE_%=;\n\t"
        "bra.uni WAIT_LOOP_%=;\n\t"
        "WAIT_DONE_%=:\n\t"
        "}" :: "r"(mbar) : "memory");
}

// ---------------------------------------------------------------------------
// Kernel 1: quantize w (256 rows) into slice-major swizzled g_wq + colsums.
// 32 CTAs x 256 thr; one warp per row.
// ---------------------------------------------------------------------------
__global__ __launch_bounds__(256)
void quant_w_kernel(const float* __restrict__ w,
                    const float* __restrict__ ws_p,
                    const float* __restrict__ wzp_p) {
    const int tid  = threadIdx.x;
    const int lane = tid & 31;
    const int warp = tid >> 5;
    const int row  = blockIdx.x * 8 + warp;   // 0..255

    const float s  = ws_p[0];
    const float zp = wzp_p[0];
    const float4* src = reinterpret_cast<const float4*>(w + (size_t)row * MDIM);
    int8_t* base = reinterpret_cast<int8_t*>(g_wq);

    float sum = 0.0f;
    const int c = lane >> 1;
    const int h = lane & 1;
    const size_t rowoff = (size_t)(((c ^ (row & 7)) << 4) + h * 8);
#pragma unroll
    for (int j = 0; j < 4; j++) {
        float4 v = src[lane + 32 * j];
        float q0 = quantize1(v.x, s, zp);
        float q1 = quantize1(v.y, s, zp);
        float q2 = quantize1(v.z, s, zp);
        float q3 = quantize1(v.w, s, zp);
        sum += q0 + q1 + q2 + q3;
        __nv_bfloat162 p01 = __floats2bfloat162_rn(q0, q1);
        __nv_bfloat162 p23 = __floats2bfloat162_rn(q2, q3);
        uint2 packed;
        packed.x = *reinterpret_cast<uint32_t*>(&p01);
        packed.y = *reinterpret_cast<uint32_t*>(&p23);
        *reinterpret_cast<uint2*>(base + ((size_t)j * KDIM + row) * SLICE_ROWB
                                  + rowoff) = packed;
    }
#pragma unroll
    for (int o = 16; o > 0; o >>= 1)
        sum += __shfl_xor_sync(0xFFFFFFFFu, sum, o);
    if (lane == 0) g_colsum[row] = sum;

    asm volatile("griddepcontrol.launch_dependents;" ::: "memory");
}

// ---------------------------------------------------------------------------
// Kernel 2: GEMM with inline x quantization.
// 128 CTAs (32m x 4n), 256 thr. A tile quantized from fp32 x into smem
// directly; B tile bulk-copied from g_wq after PDL wait.
// ---------------------------------------------------------------------------
__global__ __launch_bounds__(256, 1)
void lut_gemm_kernel(float* __restrict__ out,
                     const float* __restrict__ x,
                     const float* __restrict__ xs_p, const float* __restrict__ xzp_p,
                     const float* __restrict__ ws_p, const float* __restrict__ wzp_p) {
    extern __shared__ int8_t smem[];
    const uint32_t sbase = smem_u32(smem);
    float* rowsum_s = reinterpret_cast<float*>(smem + SM_ROWSUM);

    const int tid  = threadIdx.x;
    const int lane = tid & 31;
    const int warp = tid >> 5;

    const int m0 = (blockIdx.x >> 2) * BM;   // 32 m-tiles
    const int n0 = (blockIdx.x & 3) * BN;    // 4 n-tiles

    if (tid == 0) {
#pragma unroll
        for (int s = 0; s < NSLICE; s++)
            asm volatile("mbarrier.init.shared.b64 [%0], %1;"
                         :: "r"(sbase + s * 8), "r"(1u) : "memory");
    }

    // ===== Phase A: quantize this CTA's 64 x-rows into smem A tile =====
    // (independent of kernel1 -> overlaps it)
    const float xs  = xs_p[0];
    const float xzp = xzp_p[0];
    {
        const int c = lane >> 1;
        const int h = lane & 1;
#pragma unroll 2
        for (int it = 0; it < 8; it++) {
            const int rl = warp * 8 + it;            // local row 0..63
            const float4* src = reinterpret_cast<const float4*>(
                x + (size_t)(m0 + rl) * MDIM);
            const uint32_t rowoff =
                (uint32_t)(rl * SLICE_ROWB + (((c ^ (rl & 7)) << 4) + h * 8));
            float sum = 0.0f;
#pragma unroll
            for (int j = 0; j < 4; j++) {
                float4 v = src[lane + 32 * j];
                float q0 = quantize1(v.x, xs, xzp);
                float q1 = quantize1(v.y, xs, xzp);
                float q2 = quantize1(v.z, xs, xzp);
                float q3 = quantize1(v.w, xs, xzp);
                sum += q0 + q1 + q2 + q3;
                __nv_bfloat162 p01 = __floats2bfloat162_rn(q0, q1);
                __nv_bfloat162 p23 = __floats2bfloat162_rn(q2, q3);
                uint2 packed;
                packed.x = *reinterpret_cast<uint32_t*>(&p01);
                packed.y = *reinterpret_cast<uint32_t*>(&p23);
                *reinterpret_cast<uint2*>(
                    smem + SM_A_OFF + j * A_SL_BYTES + rowoff) = packed;
            }
#pragma unroll
            for (int o = 16; o > 0; o >>= 1)
                sum += __shfl_xor_sync(0xFFFFFFFFu, sum, o);
            if (lane == 0) rowsum_s[rl] = sum;
        }
    }
    __syncthreads();   // A tile + rowsums + mbar init visible

    // ===== Phase B: wait for w grid, then bulk-copy B slices =====
    asm volatile("griddepcontrol.wait;" ::: "memory");
    if (tid == 0) {
#pragma unroll
        for (int s = 0; s < NSLICE; s++) {
            uint32_t mbar = sbase + s * 8;
            asm volatile("mbarrier.arrive.expect_tx.shared.b64 _, [%0], %1;"
                         :: "r"(mbar), "r"((uint32_t)B_SL_BYTES) : "memory");
            const int8_t* bsrc = reinterpret_cast<const int8_t*>(g_wq)
                + ((size_t)s * KDIM + n0) * SLICE_ROWB;
            bulk_copy(sbase + SM_B_OFF + s * B_SL_BYTES, bsrc, B_SL_BYTES, mbar);
        }
    }

    // ===== Phase C: MMA loop (warp grid 2m x 4n, warp tile 32x16) =====
    const int wm = warp >> 2;       // 0..1
    const int wn = warp & 3;        // 0..3

    float acc[2][2][2][4];          // [parity][mi][ni][4]
#pragma unroll
    for (int p = 0; p < 2; p++)
#pragma unroll
        for (int mi = 0; mi < 2; mi++)
#pragma unroll
            for (int ni = 0; ni < 2; ni++)
#pragma unroll
                for (int q = 0; q < 4; q++) acc[p][mi][ni][q] = 0.0f;

    const int a_r0 = wm * 32 + (lane & 15);
    const int a_cb = lane >> 4;
    const int b_r  = wn * 16 + ((lane >> 4) << 3) + (lane & 7);
    const int b_cb = (lane >> 3) & 1;

#pragma unroll
    for (int s = 0; s < NSLICE; s++) {
        mbar_wait0(sbase + s * 8);
        const uint32_t aSl = sbase + SM_A_OFF + s * A_SL_BYTES;
        const uint32_t bSl = sbase + SM_B_OFF + s * B_SL_BYTES;

#pragma unroll
        for (int ks = 0; ks < 8; ks++) {
            const int cbase = ks * 2;
            const int p = ks & 1;
            uint32_t a[2][4];
#pragma unroll
            for (int mi = 0; mi < 2; mi++) {
                int r = a_r0 + mi * 16;
                int c = (cbase + a_cb) ^ (r & 7);
                ldsm_x4(a[mi][0], a[mi][1], a[mi][2], a[mi][3],
                        aSl + r * SLICE_ROWB + (c << 4));
            }
            uint32_t b0, b1, b2, b3;
            {
                int c = (cbase + b_cb) ^ (b_r & 7);
                ldsm_x4(b0, b1, b2, b3, bSl + b_r * SLICE_ROWB + (c << 4));
            }
#pragma unroll
            for (int mi = 0; mi < 2; mi++) {
                mma16816(acc[p][mi][0][0], acc[p][mi][0][1],
                         acc[p][mi][0][2], acc[p][mi][0][3],
                         a[mi][0], a[mi][1], a[mi][2], a[mi][3], b0, b1);
                mma16816(acc[p][mi][1][0], acc[p][mi][1][1],
                         acc[p][mi][1][2], acc[p][mi][1][3],
                         a[mi][0], a[mi][1], a[mi][2], a[mi][3], b2, b3);
            }
        }
    }

    // ===== Epilogue: merge parities + zero-point corrections + rescale =====
    const float ws  = ws_p[0];
    const float wzp = wzp_p[0];
    const float sc  = xs * ws;
    const float kconst = (float)MDIM * xzp * wzp;

#pragma unroll
    for (int mi = 0; mi < 2; mi++) {
#pragma unroll
        for (int ni = 0; ni < 2; ni++) {
            int col = n0 + wn * 16 + ni * 8 + (lane & 3) * 2;
            float cs0 = g_colsum[col];
            float cs1 = g_colsum[col + 1];
#pragma unroll
            for (int half = 0; half < 2; half++) {
                int rloc = wm * 32 + mi * 16 + (lane >> 2) + half * 8;
                float rs = rowsum_s[rloc];
                float corr = kconst - wzp * rs;
                float t0 = acc[0][mi][ni][half * 2 + 0] + acc[1][mi][ni][half * 2 + 0];
                float t1 = acc[0][mi][ni][half * 2 + 1] + acc[1][mi][ni][half * 2 + 1];
                float v0 = (t0 + corr - xzp * cs0) * sc;
                float v1 = (t1 + corr - xzp * cs1) * sc;
                *reinterpret_cast<float2*>(
                    out + (size_t)(m0 + rloc) * KDIM + col) = make_float2(v0, v1);
            }
        }
    }
}

// ---------------------------------------------------------------------------
// Launch. Inputs: x, w, lut, x_scale, x_zero_point, w_scale, w_zero_point.
// ---------------------------------------------------------------------------
extern "C" void kernel_launch(void* const* d_in, const int* in_sizes, int n_in,
                              void* d_out, int out_size) {
    const float* x   = (const float*)d_in[0];
    const float* w   = (const float*)d_in[1];
    const float* xs  = (const float*)d_in[3];
    const float* xzp = (const float*)d_in[4];
    const float* ws  = (const float*)d_in[5];
    const float* wzp = (const float*)d_in[6];
    float* out = (float*)d_out;

    cudaFuncSetAttribute(lut_gemm_kernel,
                         cudaFuncAttributeMaxDynamicSharedMemorySize, SMEM_TOTAL);

    quant_w_kernel<<<KDIM / 8, 256>>>(w, ws, wzp);

    cudaLaunchConfig_t cfg = {};
    cfg.gridDim  = dim3(128, 1, 1);
    cfg.blockDim = dim3(256, 1, 1);
    cfg.dynamicSmemBytes = SMEM_TOTAL;
    cfg.stream = 0;
    cudaLaunchAttribute attrs[1];
    attrs[0].id = cudaLaunchAttributeProgrammaticStreamSerialization;
    attrs[0].val.programmaticStreamSerializationAllowed = 1;
    cfg.attrs = attrs;
    cfg.numAttrs = 1;
    cudaLaunchKernelEx(&cfg, lut_gemm_kernel, out, x, xs, xzp, ws, wzp);
}

// round 11
// speedup vs baseline: 1.7413x; 1.7413x over previous
#include <cuda_runtime.h>
#include <cuda_bf16.h>
#include <cstdint>

// Problem shape (fixed)
#define MDIM 512            // reduction dim
#define KDIM 256            // output cols (w rows)
#define MROWS 2048          // output rows (B*N)
#define TOTROWS (MROWS + KDIM)

#define NSLICE 4
#define SLICE_ROWB 256      // bytes per row per slice (128 bf16)

// GEMM tiling: 32 m-tiles x 4 n-tiles = 128 CTAs (one wave, 1/SM)
#define BM 64
#define BN 64
#define A_SL_BYTES (BM * SLICE_ROWB)   // 16384
#define B_SL_BYTES (BN * SLICE_ROWB)   // 16384
#define STG_BYTES (A_SL_BYTES + B_SL_BYTES)  // 32768
#define SM_DATA_OFF 1024
#define SMEM_TOTAL (SM_DATA_OFF + NSLICE * STG_BYTES)   // 132096

// Scratch: bf16, SLICE-MAJOR, per-row 16B-chunk swizzle:
//   addr(row r, slice s, chunk c, half h) = (s*NROWS + r)*256 + ((c^(r&7))<<4) + h*8
__device__ __align__(16) __nv_bfloat16 g_xq[MROWS * MDIM];   // 2 MB
__device__ __align__(16) __nv_bfloat16 g_wq[KDIM * MDIM];    // 256 KB
__device__ float g_rowsum[MROWS];
__device__ float g_colsum[KDIM];

// ---------------------------------------------------------------------------
__device__ __forceinline__ float quantize1(float v, float s, float zp) {
    float q = rintf(__fadd_rn(__fdiv_rn(v, s), zp));
    return fminf(fmaxf(q, -128.0f), 127.0f);
}
__device__ __forceinline__ uint32_t smem_u32(const void* p) {
    return (uint32_t)__cvta_generic_to_shared(p);
}
__device__ __forceinline__ void ldsm_x4(uint32_t& r0, uint32_t& r1,
                                        uint32_t& r2, uint32_t& r3, uint32_t addr) {
    asm volatile("ldmatrix.sync.aligned.m8n8.x4.shared.b16 {%0,%1,%2,%3}, [%4];"
                 : "=r"(r0), "=r"(r1), "=r"(r2), "=r"(r3) : "r"(addr));
}
__device__ __forceinline__ void mma16816(float& c0, float& c1, float& c2, float& c3,
                                         uint32_t a0, uint32_t a1, uint32_t a2, uint32_t a3,
                                         uint32_t b0, uint32_t b1) {
    asm volatile(
        "mma.sync.aligned.m16n8k16.row.col.f32.bf16.bf16.f32 "
        "{%0,%1,%2,%3}, {%4,%5,%6,%7}, {%8,%9}, {%0,%1,%2,%3};"
        : "+f"(c0), "+f"(c1), "+f"(c2), "+f"(c3)
        : "r"(a0), "r"(a1), "r"(a2), "r"(a3), "r"(b0), "r"(b1));
}
__device__ __forceinline__ void bulk_copy(uint32_t sdst, const void* gsrc,
                                          uint32_t bytes, uint32_t mbar) {
    asm volatile(
        "cp.async.bulk.shared::cluster.global.mbarrier::complete_tx::bytes "
        "[%0], [%1], %2, [%3];"
        :: "r"(sdst), "l"(gsrc), "r"(bytes), "r"(mbar) : "memory");
}
__device__ __forceinline__ void mbar_wait0(uint32_t mbar) {
    asm volatile(
        "{\n\t"
        ".reg .pred P1;\n\t"
        "WAIT_LOOP_%=:\n\t"
        "mbarrier.try_wait.parity.acquire.cta.shared::cta.b64 P1, [%0], 0, 0x989680;\n\t"
        "@P1 bra.uni WAIT_DONE_%=;\n\t"
        "bra.uni WAIT_LOOP_%=;\n\t"
        "WAIT_DONE_%=:\n\t"
        "}" :: "r"(mbar) : "memory");
}

// ---------------------------------------------------------------------------
// Kernel 1: fused quantize (proven ~1.2us). rows [0,2048)=x, [2048,2304)=w.
// ---------------------------------------------------------------------------
__global__ __launch_bounds__(256)
void quant_all_kernel(const float* __restrict__ x,
                      const float* __restrict__ w,
                      const float* __restrict__ xs_p, const float* __restrict__ xzp_p,
                      const float* __restrict__ ws_p, const float* __restrict__ wzp_p) {
    __shared__ float spart[8];
    const int tid  = threadIdx.x;
    const int lane = tid & 31;
    const int wid  = tid >> 5;
    const int row  = blockIdx.x * 2 + (tid >> 7);
    const int q4   = ((tid >> 5) & 3) * 32 + lane;   // float4 index (0..127)

    const bool isX = row < MROWS;
    const float s  = isX ? xs_p[0]  : ws_p[0];
    const float zp = isX ? xzp_p[0] : wzp_p[0];
    const int lrow = isX ? row : (row - MROWS);
    const int nrows = isX ? MROWS : KDIM;
    const float* src = isX ? (x + (size_t)lrow * MDIM)
                           : (w + (size_t)lrow * MDIM);
    int8_t* base = isX ? reinterpret_cast<int8_t*>(g_xq)
                       : reinterpret_cast<int8_t*>(g_wq);

    float4 v = reinterpret_cast<const float4*>(src)[q4];
    float q0 = quantize1(v.x, s, zp);
    float q1 = quantize1(v.y, s, zp);
    float q2 = quantize1(v.z, s, zp);
    float q3 = quantize1(v.w, s, zp);
    __nv_bfloat162 p01 = __floats2bfloat162_rn(q0, q1);
    __nv_bfloat162 p23 = __floats2bfloat162_rn(q2, q3);
    uint2 packed;
    packed.x = *reinterpret_cast<uint32_t*>(&p01);
    packed.y = *reinterpret_cast<uint32_t*>(&p23);

    const int sl = q4 >> 5;
    const int c  = (q4 & 31) >> 1;
    const int h  = q4 & 1;
    size_t off = ((size_t)sl * nrows + lrow) * SLICE_ROWB
               + (size_t)(((c ^ (lrow & 7)) << 4) + h * 8);
    *reinterpret_cast<uint2*>(base + off) = packed;

    float sum = q0 + q1 + q2 + q3;
#pragma unroll
    for (int o = 16; o > 0; o >>= 1)
        sum += __shfl_xor_sync(0xFFFFFFFFu, sum, o);
    if (lane == 0) spart[wid] = sum;
    __syncthreads();
    if (tid < 2) {
        int r = blockIdx.x * 2 + tid;
        float total = spart[tid * 4 + 0] + spart[tid * 4 + 1] +
                      spart[tid * 4 + 2] + spart[tid * 4 + 3];
        if (r < MROWS) g_rowsum[r] = total;
        else           g_colsum[r - MROWS] = total;
    }
    asm volatile("griddepcontrol.launch_dependents;" ::: "memory");
}

// ---------------------------------------------------------------------------
// Kernel 2: GEMM tile 64x64, full K resident, bulk-copy loads, bf16 HMMA.
// 256 thr, warp grid 2m x 4n, warp tile 32x16, parity-split accumulators.
// ---------------------------------------------------------------------------
__global__ __launch_bounds__(256, 1)
void lut_gemm_kernel(float* __restrict__ out,
                     const float* __restrict__ xs_p, const float* __restrict__ xzp_p,
                     const float* __restrict__ ws_p, const float* __restrict__ wzp_p) {
    extern __shared__ int8_t smem[];
    const uint32_t sbase = smem_u32(smem);

    const int tid  = threadIdx.x;
    const int lane = tid & 31;
    const int warp = tid >> 5;
    const int wm = warp >> 2;       // 0..1 (32 rows)
    const int wn = warp & 3;        // 0..3 (16 cols)

    const int m0 = (blockIdx.x >> 2) * BM;   // 32 m-tiles
    const int n0 = (blockIdx.x & 3) * BN;    // 4 n-tiles

    if (tid == 0) {
#pragma unroll
        for (int s = 0; s < NSLICE; s++)
            asm volatile("mbarrier.init.shared.b64 [%0], %1;"
                         :: "r"(sbase + s * 8), "r"(1u) : "memory");
    }
    __syncthreads();

    // PDL: wait for quant grid, then issue all bulk copies.
    asm volatile("griddepcontrol.wait;" ::: "memory");
    if (tid == 0) {
#pragma unroll
        for (int s = 0; s < NSLICE; s++) {
            uint32_t mbar = sbase + s * 8;
            asm volatile("mbarrier.arrive.expect_tx.shared.b64 _, [%0], %1;"
                         :: "r"(mbar), "r"((uint32_t)STG_BYTES) : "memory");
            const int8_t* asrc = reinterpret_cast<const int8_t*>(g_xq)
                + ((size_t)s * MROWS + m0) * SLICE_ROWB;
            const int8_t* bsrc = reinterpret_cast<const int8_t*>(g_wq)
                + ((size_t)s * KDIM + n0) * SLICE_ROWB;
            uint32_t sA = sbase + SM_DATA_OFF + s * STG_BYTES;
            bulk_copy(sA, asrc, A_SL_BYTES, mbar);
            bulk_copy(sA + A_SL_BYTES, bsrc, B_SL_BYTES, mbar);
        }
    }

    // Prefetch correction sums (ready after PDL wait) to hide L2 latency.
    float rs[2][2], cs[2][2];
#pragma unroll
    for (int mi = 0; mi < 2; mi++)
#pragma unroll
        for (int half = 0; half < 2; half++)
            rs[mi][half] = g_rowsum[m0 + wm * 32 + mi * 16 + (lane >> 2) + half * 8];
#pragma unroll
    for (int ni = 0; ni < 2; ni++) {
        int col = n0 + wn * 16 + ni * 8 + (lane & 3) * 2;
        cs[ni][0] = g_colsum[col];
        cs[ni][1] = g_colsum[col + 1];
    }

    float acc[2][2][2][4];          // [parity][mi][ni][4]
#pragma unroll
    for (int p = 0; p < 2; p++)
#pragma unroll
        for (int mi = 0; mi < 2; mi++)
#pragma unroll
            for (int ni = 0; ni < 2; ni++)
#pragma unroll
                for (int q = 0; q < 4; q++) acc[p][mi][ni][q] = 0.0f;

    const int a_r0 = wm * 32 + (lane & 15);
    const int a_cb = lane >> 4;
    const int b_r  = wn * 16 + ((lane >> 4) << 3) + (lane & 7);
    const int b_cb = (lane >> 3) & 1;

#pragma unroll
    for (int s = 0; s < NSLICE; s++) {
        mbar_wait0(sbase + s * 8);
        const uint32_t aSl = sbase + SM_DATA_OFF + s * STG_BYTES;
        const uint32_t bSl = aSl + A_SL_BYTES;

#pragma unroll
        for (int ks = 0; ks < 8; ks++) {
            const int cbase = ks * 2;
            const int p = ks & 1;
            uint32_t a[2][4];
#pragma unroll
            for (int mi = 0; mi < 2; mi++) {
                int r = a_r0 + mi * 16;
                int c = (cbase + a_cb) ^ (r & 7);
                ldsm_x4(a[mi][0], a[mi][1], a[mi][2], a[mi][3],
                        aSl + r * SLICE_ROWB + (c << 4));
            }
            uint32_t b0, b1, b2, b3;
            {
                int c = (cbase + b_cb) ^ (b_r & 7);
                ldsm_x4(b0, b1, b2, b3, bSl + b_r * SLICE_ROWB + (c << 4));
            }
#pragma unroll
            for (int mi = 0; mi < 2; mi++) {
                mma16816(acc[p][mi][0][0], acc[p][mi][0][1],
                         acc[p][mi][0][2], acc[p][mi][0][3],
                         a[mi][0], a[mi][1], a[mi][2], a[mi][3], b0, b1);
                mma16816(acc[p][mi][1][0], acc[p][mi][1][1],
                         acc[p][mi][1][2], acc[p][mi][1][3],
                         a[mi][0], a[mi][1], a[mi][2], a[mi][3], b2, b3);
            }
        }
    }

    // ---- epilogue: merge parities + zero-point corrections + rescale ----
    const float xs  = xs_p[0];
    const float xzp = xzp_p[0];
    const float ws  = ws_p[0];
    const float wzp = wzp_p[0];
    const float sc  = xs * ws;
    const float kconst = (float)MDIM * xzp * wzp;

#pragma unroll
    for (int mi = 0; mi < 2; mi++) {
#pragma unroll
        for (int ni = 0; ni < 2; ni++) {
            int col = n0 + wn * 16 + ni * 8 + (lane & 3) * 2;
#pragma unroll
            for (int half = 0; half < 2; half++) {
                int row = m0 + wm * 32 + mi * 16 + (lane >> 2) + half * 8;
                float corr = kconst - wzp * rs[mi][half];
                float t0 = acc[0][mi][ni][half * 2 + 0] + acc[1][mi][ni][half * 2 + 0];
                float t1 = acc[0][mi][ni][half * 2 + 1] + acc[1][mi][ni][half * 2 + 1];
                float v0 = (t0 + corr - xzp * cs[ni][0]) * sc;
                float v1 = (t1 + corr - xzp * cs[ni][1]) * sc;
                *reinterpret_cast<float2*>(out + (size_t)row * KDIM + col) =
                    make_float2(v0, v1);
            }
        }
    }
}

// ---------------------------------------------------------------------------
// Launch. Inputs: x, w, lut, x_scale, x_zero_point, w_scale, w_zero_point.
// ---------------------------------------------------------------------------
extern "C" void kernel_launch(void* const* d_in, const int* in_sizes, int n_in,
                              void* d_out, int out_size) {
    const float* x   = (const float*)d_in[0];
    const float* w   = (const float*)d_in[1];
    const float* xs  = (const float*)d_in[3];
    const float* xzp = (const float*)d_in[4];
    const float* ws  = (const float*)d_in[5];
    const float* wzp = (const float*)d_in[6];
    float* out = (float*)d_out;

    cudaFuncSetAttribute(lut_gemm_kernel,
                         cudaFuncAttributeMaxDynamicSharedMemorySize, SMEM_TOTAL);

    quant_all_kernel<<<TOTROWS / 2, 256>>>(x, w, xs, xzp, ws, wzp);

    cudaLaunchConfig_t cfg = {};
    cfg.gridDim  = dim3(128, 1, 1);
    cfg.blockDim = dim3(256, 1, 1);
    cfg.dynamicSmemBytes = SMEM_TOTAL;
    cfg.stream = 0;
    cudaLaunchAttribute attrs[1];
    attrs[0].id = cudaLaunchAttributeProgrammaticStreamSerialization;
    attrs[0].val.programmaticStreamSerializationAllowed = 1;
    cfg.attrs = attrs;
    cfg.numAttrs = 1;
    cudaLaunchKernelEx(&cfg, lut_gemm_kernel, out, xs, xzp, ws, wzp);
}

// round 12
// speedup vs baseline: 1.7464x; 1.0029x over previous
#include <cuda_runtime.h>
#include <cuda_bf16.h>
#include <cstdint>

// Problem shape (fixed)
#define MDIM 512            // reduction dim
#define KDIM 256            // output cols (w rows)
#define MROWS 2048          // output rows (B*N)
#define TOTROWS (MROWS + KDIM)

#define NSLICE 4
#define SLICE_ROWB 256      // bytes per row per slice (128 bf16)

// GEMM tiling: 32 m-tiles x 4 n-tiles = 128 CTAs (one wave, 1/SM)
#define BM 64
#define BN 64
#define A_SL_BYTES (BM * SLICE_ROWB)   // 16384
#define B_SL_BYTES (BN * SLICE_ROWB)   // 16384
#define STG_BYTES (A_SL_BYTES + B_SL_BYTES)  // 32768
#define SM_DATA_OFF 1024
#define SMEM_TOTAL (SM_DATA_OFF + NSLICE * STG_BYTES)   // 132096

// Scratch: bf16, SLICE-MAJOR, per-row 16B-chunk swizzle:
//   addr(row r, slice s, chunk c, half h) = (s*NROWS + r)*256 + ((c^(r&7))<<4) + h*8
__device__ __align__(16) __nv_bfloat16 g_xq[MROWS * MDIM];   // 2 MB
__device__ __align__(16) __nv_bfloat16 g_wq[KDIM * MDIM];    // 256 KB
__device__ float g_rowsum[MROWS];
__device__ float g_colsum[KDIM];

// ---------------------------------------------------------------------------
__device__ __forceinline__ float quantize1(float v, float s, float zp) {
    float q = rintf(__fadd_rn(__fdiv_rn(v, s), zp));
    return fminf(fmaxf(q, -128.0f), 127.0f);
}
__device__ __forceinline__ uint32_t smem_u32(const void* p) {
    return (uint32_t)__cvta_generic_to_shared(p);
}
__device__ __forceinline__ void ldsm_x4(uint32_t& r0, uint32_t& r1,
                                        uint32_t& r2, uint32_t& r3, uint32_t addr) {
    asm volatile("ldmatrix.sync.aligned.m8n8.x4.shared.b16 {%0,%1,%2,%3}, [%4];"
                 : "=r"(r0), "=r"(r1), "=r"(r2), "=r"(r3) : "r"(addr));
}
__device__ __forceinline__ void mma16816(float& c0, float& c1, float& c2, float& c3,
                                         uint32_t a0, uint32_t a1, uint32_t a2, uint32_t a3,
                                         uint32_t b0, uint32_t b1) {
    asm volatile(
        "mma.sync.aligned.m16n8k16.row.col.f32.bf16.bf16.f32 "
        "{%0,%1,%2,%3}, {%4,%5,%6,%7}, {%8,%9}, {%0,%1,%2,%3};"
        : "+f"(c0), "+f"(c1), "+f"(c2), "+f"(c3)
        : "r"(a0), "r"(a1), "r"(a2), "r"(a3), "r"(b0), "r"(b1));
}
__device__ __forceinline__ void bulk_copy(uint32_t sdst, const void* gsrc,
                                          uint32_t bytes, uint32_t mbar) {
    asm volatile(
        "cp.async.bulk.shared::cluster.global.mbarrier::complete_tx::bytes "
        "[%0], [%1], %2, [%3];"
        :: "r"(sdst), "l"(gsrc), "r"(bytes), "r"(mbar) : "memory");
}
__device__ __forceinline__ void mbar_wait0(uint32_t mbar) {
    asm volatile(
        "{\n\t"
        ".reg .pred P1;\n\t"
        "WAIT_LOOP_%=:\n\t"
        "mbarrier.try_wait.parity.acquire.cta.shared::cta.b64 P1, [%0], 0, 0x989680;\n\t"
        "@P1 bra.uni WAIT_DONE_%=;\n\t"
        "bra.uni WAIT_LOOP_%=;\n\t"
        "WAIT_DONE_%=:\n\t"
        "}" :: "r"(mbar) : "memory");
}

// ---------------------------------------------------------------------------
// Kernel 1: fused quantize (proven). rows [0,2048)=x, [2048,2304)=w.
// ---------------------------------------------------------------------------
__global__ __launch_bounds__(256)
void quant_all_kernel(const float* __restrict__ x,
                      const float* __restrict__ w,
                      const float* __restrict__ xs_p, const float* __restrict__ xzp_p,
                      const float* __restrict__ ws_p, const float* __restrict__ wzp_p) {
    __shared__ float spart[8];
    const int tid  = threadIdx.x;
    const int lane = tid & 31;
    const int wid  = tid >> 5;
    const int row  = blockIdx.x * 2 + (tid >> 7);
    const int q4   = ((tid >> 5) & 3) * 32 + lane;   // float4 index (0..127)

    const bool isX = row < MROWS;
    const float s  = isX ? xs_p[0]  : ws_p[0];
    const float zp = isX ? xzp_p[0] : wzp_p[0];
    const int lrow = isX ? row : (row - MROWS);
    const int nrows = isX ? MROWS : KDIM;
    const float* src = isX ? (x + (size_t)lrow * MDIM)
                           : (w + (size_t)lrow * MDIM);
    int8_t* base = isX ? reinterpret_cast<int8_t*>(g_xq)
                       : reinterpret_cast<int8_t*>(g_wq);

    float4 v = reinterpret_cast<const float4*>(src)[q4];
    float q0 = quantize1(v.x, s, zp);
    float q1 = quantize1(v.y, s, zp);
    float q2 = quantize1(v.z, s, zp);
    float q3 = quantize1(v.w, s, zp);
    __nv_bfloat162 p01 = __floats2bfloat162_rn(q0, q1);
    __nv_bfloat162 p23 = __floats2bfloat162_rn(q2, q3);
    uint2 packed;
    packed.x = *reinterpret_cast<uint32_t*>(&p01);
    packed.y = *reinterpret_cast<uint32_t*>(&p23);

    const int sl = q4 >> 5;
    const int c  = (q4 & 31) >> 1;
    const int h  = q4 & 1;
    size_t off = ((size_t)sl * nrows + lrow) * SLICE_ROWB
               + (size_t)(((c ^ (lrow & 7)) << 4) + h * 8);
    *reinterpret_cast<uint2*>(base + off) = packed;

    float sum = q0 + q1 + q2 + q3;
#pragma unroll
    for (int o = 16; o > 0; o >>= 1)
        sum += __shfl_xor_sync(0xFFFFFFFFu, sum, o);
    if (lane == 0) spart[wid] = sum;
    __syncthreads();
    if (tid < 2) {
        int r = blockIdx.x * 2 + tid;
        float total = spart[tid * 4 + 0] + spart[tid * 4 + 1] +
                      spart[tid * 4 + 2] + spart[tid * 4 + 3];
        if (r < MROWS) g_rowsum[r] = total;
        else           g_colsum[r - MROWS] = total;
    }
    asm volatile("griddepcontrol.launch_dependents;" ::: "memory");
}

// ---------------------------------------------------------------------------
// Kernel 2: GEMM tile 64x64, full K resident, bulk-copy loads, bf16 HMMA.
// 512 thr, warp grid 4m x 4n, warp tile 16x16, parity-split accumulators.
// 16 warps/SM (4 per SMSP) for latency coverage.
// ---------------------------------------------------------------------------
__global__ __launch_bounds__(512, 1)
void lut_gemm_kernel(float* __restrict__ out,
                     const float* __restrict__ xs_p, const float* __restrict__ xzp_p,
                     const float* __restrict__ ws_p, const float* __restrict__ wzp_p) {
    extern __shared__ int8_t smem[];
    const uint32_t sbase = smem_u32(smem);

    const int tid  = threadIdx.x;
    const int lane = tid & 31;
    const int warp = tid >> 5;
    const int wm = warp >> 2;       // 0..3 (16 rows each)
    const int wn = warp & 3;        // 0..3 (16 cols each)

    const int m0 = (blockIdx.x >> 2) * BM;   // 32 m-tiles
    const int n0 = (blockIdx.x & 3) * BN;    // 4 n-tiles

    if (tid == 0) {
#pragma unroll
        for (int s = 0; s < NSLICE; s++)
            asm volatile("mbarrier.init.shared.b64 [%0], %1;"
                         :: "r"(sbase + s * 8), "r"(1u) : "memory");
    }
    __syncthreads();

    // PDL: wait for quant grid, then issue all bulk copies.
    asm volatile("griddepcontrol.wait;" ::: "memory");
    if (tid == 0) {
#pragma unroll
        for (int s = 0; s < NSLICE; s++) {
            uint32_t mbar = sbase + s * 8;
            asm volatile("mbarrier.arrive.expect_tx.shared.b64 _, [%0], %1;"
                         :: "r"(mbar), "r"((uint32_t)STG_BYTES) : "memory");
            const int8_t* asrc = reinterpret_cast<const int8_t*>(g_xq)
                + ((size_t)s * MROWS + m0) * SLICE_ROWB;
            const int8_t* bsrc = reinterpret_cast<const int8_t*>(g_wq)
                + ((size_t)s * KDIM + n0) * SLICE_ROWB;
            uint32_t sA = sbase + SM_DATA_OFF + s * STG_BYTES;
            bulk_copy(sA, asrc, A_SL_BYTES, mbar);
            bulk_copy(sA + A_SL_BYTES, bsrc, B_SL_BYTES, mbar);
        }
    }

    // Prefetch correction sums (ready after PDL wait) to hide L2 latency.
    float rs[2], cs[2][2];
#pragma unroll
    for (int half = 0; half < 2; half++)
        rs[half] = g_rowsum[m0 + wm * 16 + (lane >> 2) + half * 8];
#pragma unroll
    for (int ni = 0; ni < 2; ni++) {
        int col = n0 + wn * 16 + ni * 8 + (lane & 3) * 2;
        cs[ni][0] = g_colsum[col];
        cs[ni][1] = g_colsum[col + 1];
    }

    float acc[2][2][4];             // [parity][ni][4]
#pragma unroll
    for (int p = 0; p < 2; p++)
#pragma unroll
        for (int ni = 0; ni < 2; ni++)
#pragma unroll
            for (int q = 0; q < 4; q++) acc[p][ni][q] = 0.0f;

    const int a_r  = wm * 16 + (lane & 15);
    const int a_cb = lane >> 4;                 // A k-half chunk bit
    const int b_r  = wn * 16 + ((lane >> 4) << 3) + (lane & 7);
    const int b_cb = (lane >> 3) & 1;           // B k-half chunk bit

#pragma unroll
    for (int s = 0; s < NSLICE; s++) {
        mbar_wait0(sbase + s * 8);
        const uint32_t aSl = sbase + SM_DATA_OFF + s * STG_BYTES;
        const uint32_t bSl = aSl + A_SL_BYTES;

#pragma unroll
        for (int ks = 0; ks < 8; ks++) {        // 8 k16 steps per slice
            const int cbase = ks * 2;
            const int p = ks & 1;
            uint32_t a0, a1, a2, a3;
            {
                int c = (cbase + a_cb) ^ (a_r & 7);
                ldsm_x4(a0, a1, a2, a3, aSl + a_r * SLICE_ROWB + (c << 4));
            }
            uint32_t b0, b1, b2, b3;
            {
                int c = (cbase + b_cb) ^ (b_r & 7);
                ldsm_x4(b0, b1, b2, b3, bSl + b_r * SLICE_ROWB + (c << 4));
            }
            mma16816(acc[p][0][0], acc[p][0][1], acc[p][0][2], acc[p][0][3],
                     a0, a1, a2, a3, b0, b1);
            mma16816(acc[p][1][0], acc[p][1][1], acc[p][1][2], acc[p][1][3],
                     a0, a1, a2, a3, b2, b3);
        }
    }

    // ---- epilogue: merge parities + zero-point corrections + rescale ----
    const float xs  = xs_p[0];
    const float xzp = xzp_p[0];
    const float ws  = ws_p[0];
    const float wzp = wzp_p[0];
    const float sc  = xs * ws;
    const float kconst = (float)MDIM * xzp * wzp;

#pragma unroll
    for (int ni = 0; ni < 2; ni++) {
        int col = n0 + wn * 16 + ni * 8 + (lane & 3) * 2;
#pragma unroll
        for (int half = 0; half < 2; half++) {
            int row = m0 + wm * 16 + (lane >> 2) + half * 8;
            float corr = kconst - wzp * rs[half];
            float t0 = acc[0][ni][half * 2 + 0] + acc[1][ni][half * 2 + 0];
            float t1 = acc[0][ni][half * 2 + 1] + acc[1][ni][half * 2 + 1];
            float v0 = (t0 + corr - xzp * cs[ni][0]) * sc;
            float v1 = (t1 + corr - xzp * cs[ni][1]) * sc;
            *reinterpret_cast<float2*>(out + (size_t)row * KDIM + col) =
                make_float2(v0, v1);
        }
    }
}

// ---------------------------------------------------------------------------
// Launch. Inputs: x, w, lut, x_scale, x_zero_point, w_scale, w_zero_point.
// ---------------------------------------------------------------------------
extern "C" void kernel_launch(void* const* d_in, const int* in_sizes, int n_in,
                              void* d_out, int out_size) {
    const float* x   = (const float*)d_in[0];
    const float* w   = (const float*)d_in[1];
    const float* xs  = (const float*)d_in[3];
    const float* xzp = (const float*)d_in[4];
    const float* ws  = (const float*)d_in[5];
    const float* wzp = (const float*)d_in[6];
    float* out = (float*)d_out;

    cudaFuncSetAttribute(lut_gemm_kernel,
                         cudaFuncAttributeMaxDynamicSharedMemorySize, SMEM_TOTAL);

    quant_all_kernel<<<TOTROWS / 2, 256>>>(x, w, xs, xzp, ws, wzp);

    cudaLaunchConfig_t cfg = {};
    cfg.gridDim  = dim3(128, 1, 1);
    cfg.blockDim = dim3(512, 1, 1);
    cfg.dynamicSmemBytes = SMEM_TOTAL;
    cfg.stream = 0;
    cudaLaunchAttribute attrs[1];
    attrs[0].id = cudaLaunchAttributeProgrammaticStreamSerialization;
    attrs[0].val.programmaticStreamSerializationAllowed = 1;
    cfg.attrs = attrs;
    cfg.numAttrs = 1;
    cudaLaunchKernelEx(&cfg, lut_gemm_kernel, out, xs, xzp, ws, wzp);
}